// round 7
// baseline (speedup 1.0000x reference)
#include <cuda_runtime.h>
#include <math.h>

// Problem constants
#define TT   128
#define BB   64
#define INS  128
#define HH   512
#define NN   2048
#define WW   64
#define OO   128
#define RRh  4
#define CTRL (INS + RRh*WW)      // 384
#define NH   (OO + (RRh+1)*WW)   // 448
#define EPSF 1e-8f

#define GRID 256                 // 2 CTAs/SM co-resident
#define NTH  256
#define KSPL 8                   // gates GEMM split-K
#define DYN_FLOATS 18304         // 73216 B dynamic smem per CTA

// Persistent device state (no allocations allowed)
__device__ float g_M[BB*NN*WW];            // 33.5 MB memory matrix
__device__ float g_h[2][BB*HH];            // double-buffered hidden state
__device__ float g_c[BB*HH];
__device__ float g_usage[BB*NN];
__device__ float g_rw[2][BB*RRh*NN];       // read weights (raw sim -> softmaxed)
__device__ float g_readvec[BB*RRh*WW];
__device__ float g_gates_part[KSPL][BB*4*HH];
__device__ float g_heads[BB*NH];
__device__ float g_rv_part[BB*8*256];      // per-(b,tile) read_vec partials
__device__ float4 g_smx[BB*8];             // per-(b,tile) softmax tile max (r0..r3)
__device__ float4 g_sms[BB*8];             // per-(b,tile) softmax tile sumexp
__device__ int   g_lu[BB];                 // least-used slot per batch
__device__ unsigned g_cnt1[32];            // gates-tile completion counters
__device__ unsigned g_cnt6[BB];            // update-tile completion counters
__device__ unsigned g_arrive;              // monotonic barrier counter

__device__ __forceinline__ float sigm(float x){ return 1.f/(1.f+expf(-x)); }

// Grid barrier: monotonic cumulative counter -> replay-safe, no reset race.
__device__ __forceinline__ void gsync(){
    __syncthreads();
    if (threadIdx.x == 0){
        __threadfence();
        unsigned old = atomicAdd(&g_arrive, 1u);
        unsigned target = (old/GRID + 1u)*GRID;
        while (*(volatile unsigned*)&g_arrive < target) { }
        __threadfence();
    }
    __syncthreads();
}

__global__ __launch_bounds__(NTH, 2) void mann_persistent(
    const float* __restrict__ x,    const float* __restrict__ Wih,
    const float* __restrict__ Whh,  const float* __restrict__ bih,
    const float* __restrict__ bhh,  const float* __restrict__ Wout,
    const float* __restrict__ bout, const float* __restrict__ Wkey,
    const float* __restrict__ bkey, const float* __restrict__ alpha_p,
    const float* __restrict__ gamma_p, float* __restrict__ out)
{
    extern __shared__ float dyn[];
    __shared__ int s_flag;
    const int c    = blockIdx.x;
    const int tid  = threadIdx.x;
    const int lane = tid & 31, warp = tid >> 5;

    // ------------------- init (graph replays re-run this) --------------------
    for (int i = c*NTH + tid; i < BB*NN*WW;  i += GRID*NTH) g_M[i] = 1e-6f;
    for (int i = c*NTH + tid; i < BB*HH;     i += GRID*NTH){
        g_h[0][i]=0.f; g_h[1][i]=0.f; g_c[i]=0.f;
    }
    for (int i = c*NTH + tid; i < BB*NN;     i += GRID*NTH) g_usage[i]=0.f;
    for (int i = c*NTH + tid; i < BB*RRh*NN; i += GRID*NTH){ g_rw[0][i]=0.f; g_rw[1][i]=0.f; }
    for (int i = c*NTH + tid; i < BB*RRh*WW; i += GRID*NTH) g_readvec[i]=0.f;
    if (c == 0 && tid < BB){ g_lu[tid] = 0; g_cnt6[tid] = 0u; }
    if (c == 1 && tid < 32) g_cnt1[tid] = 0u;
    const float sa  = sigm(alpha_p[0]);
    const float gam = gamma_p[0];
    gsync();

    for (int t = 0; t < TT; t++){
        const int cur = t & 1, prev = cur ^ 1;
        const int hc = t & 1, hp = hc ^ 1;     // h double buffer
        const float* xt = x + (size_t)t*BB*INS;
        const unsigned tgt = 8u*(unsigned)t + 7u;

        // ===== Phase 1: gates GEMM (gate-aligned tiles) + LSTM tail ==========
        // CTA -> u-block ub=(c&31) covering 16 h-cols x 4 gates = 64 gate cols;
        // k-split ks=(c>>5). Last-of-8 CTA per ub runs the LSTM pointwise.
        {
            float* As = dyn;            // [64][17] row = batch
            float* Bs = dyn + 1088;     // [64][17] row = cc (gate-col slot)
            const int ub = c & 31;
            const int ks = c >> 5;
            const int tx = tid & 15, ty = tid >> 4;
            const float* hpp = g_h[hp];
            float acc[4][4] = {};
            for (int kt = 0; kt < 7; kt++){
                const int kb = ks*112 + kt*16;
                #pragma unroll
                for (int jj = 0; jj < 4; jj++){
                    int e = tid + jj*256;
                    int row = e >> 4, kk = e & 15, gk = kb + kk;
                    float a;
                    if (gk < INS)       a = xt[row*INS + gk];
                    else if (gk < CTRL) a = g_readvec[row*256 + gk - INS];
                    else                a = hpp[row*HH + gk - CTRL];
                    As[row*17 + kk] = a;
                    int cc = row;
                    int n = (cc >> 4)*512 + ub*16 + (cc & 15);
                    Bs[cc*17 + kk] = (gk < CTRL) ? Wih[n*CTRL + gk]
                                                 : Whh[n*HH + gk - CTRL];
                }
                __syncthreads();
                #pragma unroll
                for (int kk = 0; kk < 16; kk++){
                    float a[4], b[4];
                    #pragma unroll
                    for (int i = 0; i < 4; i++) a[i] = As[(ty*4+i)*17 + kk];
                    #pragma unroll
                    for (int j = 0; j < 4; j++) b[j] = Bs[(tx*4+j)*17 + kk];
                    #pragma unroll
                    for (int i = 0; i < 4; i++)
                        #pragma unroll
                        for (int j = 0; j < 4; j++)
                            acc[i][j] += a[i]*b[j];
                }
                __syncthreads();
            }
            float* outp = g_gates_part[ks];
            #pragma unroll
            for (int i = 0; i < 4; i++)
                #pragma unroll
                for (int j = 0; j < 4; j++){
                    int cc = tx*4 + j;
                    int n = (cc >> 4)*512 + ub*16 + (cc & 15);
                    outp[(ty*4+i)*(4*HH) + n] = acc[i][j];
                }
            // ---- LSTM tail (last-of-8 split-K CTAs for this u-block) ----
            __threadfence();
            __syncthreads();
            if (tid == 0){
                unsigned old = atomicAdd(&g_cnt1[ub], 1u);
                s_flag = (old == tgt);
            }
            __syncthreads();
            if (s_flag){
                __threadfence();
                float* hcp = g_h[hc];
                #pragma unroll
                for (int q = 0; q < 4; q++){
                    int e = tid + q*256;             // 0..1023 = b*16 + uu
                    int b = e >> 4, uu = e & 15;
                    int u = ub*16 + uu;
                    float gs[4];
                    #pragma unroll
                    for (int g = 0; g < 4; g++){
                        int col = b*(4*HH) + g*512 + u;
                        float s0 = 0.f;
                        #pragma unroll
                        for (int p = 0; p < KSPL; p++) s0 += g_gates_part[p][col];
                        gs[g] = s0 + bih[g*512+u] + bhh[g*512+u];
                    }
                    int hi = b*HH + u;
                    float cv = sigm(gs[1])*g_c[hi] + sigm(gs[0])*tanhf(gs[2]);
                    g_c[hi] = cv;
                    hcp[hi] = sigm(gs[3])*tanhf(cv);
                }
            }
        }
        gsync();

        // ===== Phase 2: heads GEMM C[64,448], K=512, 2 cols/CTA, split-K 2 ====
        if (c < 224){
            float* hs  = dyn;                // [64][65]
            float* ws  = dyn + 64*65;        // [2][65]
            float* red = dyn + 64*65 + 130;  // [256]
            const int n0c = c*2;
            const int b  = tid & 63, q = tid >> 6;       // q: (col,khalf)
            const int col = n0c + (q >> 1), kh = q & 1;
            const float* hcp = g_h[hc];
            float acc = 0.f;
            for (int kt = 0; kt < 8; kt++){
                const int kb = kt*64;
                #pragma unroll
                for (int i2 = 0; i2 < 16; i2++){
                    int idx = tid + i2*NTH;
                    int row = idx >> 6, kc = idx & 63;
                    hs[row*65 + kc] = hcp[row*HH + kb + kc];
                }
                if (tid < 128){
                    int wn = tid >> 6, kc = tid & 63;
                    int gn = n0c + wn;
                    ws[wn*65 + kc] = (gn < OO) ? Wout[gn*HH + kb + kc]
                                               : Wkey[(gn-OO)*HH + kb + kc];
                }
                __syncthreads();
                if ((kt >> 2) == kh){
                    #pragma unroll
                    for (int k = 0; k < 64; k++)
                        acc += hs[b*65 + k] * ws[(q>>1)*65 + k];
                }
                __syncthreads();
            }
            red[tid] = acc;
            __syncthreads();
            if (kh == 0){
                float v = red[tid] + red[tid + 64];
                v += (col < OO) ? bout[col] : bkey[col - OO];
                g_heads[b*NH + col] = v;
                if (col < OO) out[(size_t)t*BB*OO + b*OO + col] = v;
            }
        }
        gsync();

        // ===== Phase 3: similarity (raw) + softmax tile partials ==============
        // 512 units = b(64) x tile(8 of 256 rows); 2 units per CTA
        {
            float*  Ms   = dyn;                      // [256][65]
            float*  Kn4  = dyn + 16640;              // [64][4]
            float4* wred = (float4*)(dyn + 16896);   // [8]
            float4* bc4  = (float4*)(dyn + 16928);   // [1]
            #pragma unroll 1
            for (int j = 0; j < 2; j++){
                const int unit = c + j*GRID;
                const int b = unit >> 3, tile = unit & 7;
                const int n0 = tile*256;
                if (warp < RRh){
                    const float* kp = &g_heads[b*NH + OO + warp*WW];
                    float k0 = kp[lane], k1 = kp[lane+32];
                    float ss = k0*k0 + k1*k1;
                    #pragma unroll
                    for (int o = 16; o; o >>= 1) ss += __shfl_xor_sync(0xffffffffu, ss, o);
                    float inv = 1.f/(sqrtf(ss) + EPSF);
                    Kn4[lane*4 + warp]      = k0*inv;
                    Kn4[(lane+32)*4 + warp] = k1*inv;
                }
                const float4* Mg = (const float4*)&g_M[((size_t)b*NN + n0)*WW];
                #pragma unroll
                for (int i = 0; i < 16; i++){
                    int idx = tid + i*256;
                    int row = idx >> 4, wq = idx & 15;
                    float4 v = Mg[idx];
                    float* d = &Ms[row*65 + wq*4];
                    d[0] = v.x; d[1] = v.y; d[2] = v.z; d[3] = v.w;
                }
                __syncthreads();
                float s = 0.f, d0 = 0.f, d1 = 0.f, d2 = 0.f, d3 = 0.f;
                const float* Mr = &Ms[tid*65];
                #pragma unroll 8
                for (int w = 0; w < 64; w++){
                    float m = Mr[w];
                    float4 k = *(const float4*)&Kn4[w*4];
                    s  += m*m;
                    d0 += k.x*m; d1 += k.y*m; d2 += k.z*m; d3 += k.w*m;
                }
                float inv = 1.f/(sqrtf(s) + EPSF);
                float s0 = d0*inv, s1 = d1*inv, s2 = d2*inv, s3 = d3*inv;
                float* simp = &g_rw[cur][(size_t)b*RRh*NN + n0 + tid];
                simp[0]    = s0;
                simp[NN]   = s1;
                simp[2*NN] = s2;
                simp[3*NN] = s3;
                // --- tile max (per r) via warp shfl + 8-lane combine ---
                float4 mv = make_float4(s0, s1, s2, s3);
                #pragma unroll
                for (int o = 16; o; o >>= 1){
                    mv.x = fmaxf(mv.x, __shfl_xor_sync(0xffffffffu, mv.x, o));
                    mv.y = fmaxf(mv.y, __shfl_xor_sync(0xffffffffu, mv.y, o));
                    mv.z = fmaxf(mv.z, __shfl_xor_sync(0xffffffffu, mv.z, o));
                    mv.w = fmaxf(mv.w, __shfl_xor_sync(0xffffffffu, mv.w, o));
                }
                if (lane == 0) wred[warp] = mv;
                __syncthreads();
                if (tid < 8){
                    float4 m = wred[tid];
                    #pragma unroll
                    for (int o = 4; o; o >>= 1){
                        m.x = fmaxf(m.x, __shfl_xor_sync(0xffu, m.x, o));
                        m.y = fmaxf(m.y, __shfl_xor_sync(0xffu, m.y, o));
                        m.z = fmaxf(m.z, __shfl_xor_sync(0xffu, m.z, o));
                        m.w = fmaxf(m.w, __shfl_xor_sync(0xffu, m.w, o));
                    }
                    if (tid == 0) bc4[0] = m;
                }
                __syncthreads();
                float4 tm = bc4[0];
                // --- tile sumexp (per r) ---
                float4 ev = make_float4(expf(s0-tm.x), expf(s1-tm.y),
                                        expf(s2-tm.z), expf(s3-tm.w));
                #pragma unroll
                for (int o = 16; o; o >>= 1){
                    ev.x += __shfl_xor_sync(0xffffffffu, ev.x, o);
                    ev.y += __shfl_xor_sync(0xffffffffu, ev.y, o);
                    ev.z += __shfl_xor_sync(0xffffffffu, ev.z, o);
                    ev.w += __shfl_xor_sync(0xffffffffu, ev.w, o);
                }
                if (lane == 0) wred[warp] = ev;
                __syncthreads();
                if (tid < 8){
                    float4 sv = wred[tid];
                    #pragma unroll
                    for (int o = 4; o; o >>= 1){
                        sv.x += __shfl_xor_sync(0xffu, sv.x, o);
                        sv.y += __shfl_xor_sync(0xffu, sv.y, o);
                        sv.z += __shfl_xor_sync(0xffu, sv.z, o);
                        sv.w += __shfl_xor_sync(0xffu, sv.w, o);
                    }
                    if (tid == 0){ g_smx[unit] = tm; g_sms[unit] = sv; }
                }
                __syncthreads();
            }
        }
        gsync();

        // ===== Phase 4: update (softmax-inline) + rv/argmin tail ==============
        {
            float*  Ms    = dyn;                     // [256][65]
            float*  rcs   = dyn + 16640;             // [4][256]
            float*  wwv   = dyn + 17664;             // [256]
            float*  keepv = dyn + 17920;             // [256]
            float*  wkv   = dyn + 18176;             // [64]
            float4* bc4   = (float4*)(dyn + 18240);  // [0]=gmax [1]=invZ
            #pragma unroll 1
            for (int j = 0; j < 2; j++){
                const int unit = c + j*GRID;
                const int b = unit >> 3, tile = unit & 7;
                const int n0 = tile*256;
                const int lu = g_lu[b];
                // global softmax stats from 8 tile partials
                if (tid < 8){
                    float4 m = g_smx[b*8 + tid];
                    float4 s = g_sms[b*8 + tid];
                    float4 gm = m;
                    #pragma unroll
                    for (int o = 4; o; o >>= 1){
                        gm.x = fmaxf(gm.x, __shfl_xor_sync(0xffu, gm.x, o));
                        gm.y = fmaxf(gm.y, __shfl_xor_sync(0xffu, gm.y, o));
                        gm.z = fmaxf(gm.z, __shfl_xor_sync(0xffu, gm.z, o));
                        gm.w = fmaxf(gm.w, __shfl_xor_sync(0xffu, gm.w, o));
                    }
                    float4 z;
                    z.x = s.x*expf(m.x - gm.x);
                    z.y = s.y*expf(m.y - gm.y);
                    z.z = s.z*expf(m.z - gm.z);
                    z.w = s.w*expf(m.w - gm.w);
                    #pragma unroll
                    for (int o = 4; o; o >>= 1){
                        z.x += __shfl_xor_sync(0xffu, z.x, o);
                        z.y += __shfl_xor_sync(0xffu, z.y, o);
                        z.z += __shfl_xor_sync(0xffu, z.z, o);
                        z.w += __shfl_xor_sync(0xffu, z.w, o);
                    }
                    if (tid == 0){
                        bc4[0] = gm;
                        bc4[1] = make_float4(1.f/z.x, 1.f/z.y, 1.f/z.z, 1.f/z.w);
                    }
                }
                // stage M tile
                const float4* Mg = (const float4*)&g_M[((size_t)b*NN + n0)*WW];
                #pragma unroll
                for (int i = 0; i < 16; i++){
                    int idx = tid + i*256;
                    int row = idx >> 4, wq = idx & 15;
                    float4 v = Mg[idx];
                    float* d = &Ms[row*65 + wq*4];
                    d[0] = v.x; d[1] = v.y; d[2] = v.z; d[3] = v.w;
                }
                __syncthreads();
                // softmax-inline read weights; stage rc; w_w/keep/usage
                {
                    float4 gm = bc4[0], iz = bc4[1];
                    float* rawp = &g_rw[cur][(size_t)b*RRh*NN + n0];
                    const float* rp = &g_rw[prev][(size_t)b*RRh*NN + n0];
                    float r0 = expf(rawp[tid]      - gm.x)*iz.x;
                    float r1 = expf(rawp[NN+tid]   - gm.y)*iz.y;
                    float r2 = expf(rawp[2*NN+tid] - gm.z)*iz.z;
                    float r3 = expf(rawp[3*NN+tid] - gm.w)*iz.w;
                    rawp[tid]      = r0;   // write back: next step's prev
                    rawp[NN+tid]   = r1;
                    rawp[2*NN+tid] = r2;
                    rawp[3*NN+tid] = r3;
                    rcs[tid] = r0; rcs[256+tid] = r1; rcs[512+tid] = r2; rcs[768+tid] = r3;
                    float ps = rp[tid] + rp[NN+tid] + rp[2*NN+tid] + rp[3*NN+tid];
                    float isLu = ((n0 + tid) == lu) ? 1.f : 0.f;
                    float ww = sa*ps + (1.f-sa)*isLu;
                    wwv[tid]   = ww;
                    keepv[tid] = 1.f - isLu;
                    int un = b*NN + n0 + tid;
                    g_usage[un] = gam*g_usage[un] + (r0+r1+r2+r3) + ww;
                    if (tid < WW) wkv[tid] = g_heads[b*NH + OO + RRh*WW + tid];
                }
                __syncthreads();
                // rv partial (old M) : thread (r,w)
                {
                    const int r = tid >> 6, w = tid & 63;
                    const float* rcr = &rcs[r*256];
                    float acc = 0.f;
                    #pragma unroll 8
                    for (int n = 0; n < 256; n++)
                        acc += rcr[n] * Ms[n*65 + w];
                    g_rv_part[(b*8 + tile)*256 + tid] = acc;
                }
                // M rewrite
                {
                    float4* Mo = (float4*)&g_M[((size_t)b*NN + n0)*WW];
                    #pragma unroll
                    for (int i = 0; i < 16; i++){
                        int idx = tid + i*256;
                        int row = idx >> 4, wq = idx & 15;
                        const float* m = &Ms[row*65 + wq*4];
                        float kr = keepv[row], ww = wwv[row];
                        float4 o;
                        o.x = m[0]*kr + ww*wkv[wq*4+0];
                        o.y = m[1]*kr + ww*wkv[wq*4+1];
                        o.z = m[2]*kr + ww*wkv[wq*4+2];
                        o.w = m[3]*kr + ww*wkv[wq*4+3];
                        Mo[idx] = o;
                    }
                }
                // ---- tail: last-of-8 tiles for b -> rv reduce + argmin ----
                __threadfence();
                __syncthreads();
                if (tid == 0){
                    unsigned old = atomicAdd(&g_cnt6[b], 1u);
                    s_flag = (old == tgt);
                }
                __syncthreads();
                if (s_flag){
                    __threadfence();
                    float s = 0.f;
                    #pragma unroll
                    for (int tl = 0; tl < 8; tl++)
                        s += g_rv_part[(b*8 + tl)*256 + tid];
                    g_readvec[b*256 + tid] = s;

                    float* sv = rcs;             // reuse (done with rcs)
                    int*   si = (int*)wwv;       // reuse
                    float bv = 3.4e38f; int bi = 0x7fffffff;
                    #pragma unroll
                    for (int jj = 0; jj < 8; jj++){
                        int n = tid + jj*256;
                        float v = g_usage[b*NN + n];
                        if (v < bv || (v == bv && n < bi)){ bv = v; bi = n; }
                    }
                    sv[tid] = bv; si[tid] = bi; __syncthreads();
                    for (int st = 128; st; st >>= 1){
                        if (tid < st){
                            float v2 = sv[tid+st]; int i2 = si[tid+st];
                            if (v2 < sv[tid] || (v2 == sv[tid] && i2 < si[tid])){
                                sv[tid] = v2; si[tid] = i2;
                            }
                        }
                        __syncthreads();
                    }
                    if (tid == 0) g_lu[b] = si[0];
                }
                __syncthreads();
            }
        }
        gsync();
    }
}

// ---------------------------------------------------------------------------
extern "C" void kernel_launch(void* const* d_in, const int* in_sizes, int n_in,
                              void* d_out, int out_size){
    const float* x     = (const float*)d_in[0];
    const float* Wih   = (const float*)d_in[1];
    const float* Whh   = (const float*)d_in[2];
    const float* bih   = (const float*)d_in[3];
    const float* bhh   = (const float*)d_in[4];
    const float* Wout  = (const float*)d_in[5];
    const float* bout  = (const float*)d_in[6];
    const float* Wkey  = (const float*)d_in[7];
    const float* bkey  = (const float*)d_in[8];
    const float* alpha = (const float*)d_in[9];
    const float* gma   = (const float*)d_in[10];
    float* out = (float*)d_out;

    cudaFuncSetAttribute(mann_persistent,
                         cudaFuncAttributeMaxDynamicSharedMemorySize,
                         DYN_FLOATS*4);
    mann_persistent<<<GRID, NTH, DYN_FLOATS*4>>>(x, Wih, Whh, bih, bhh,
                                                 Wout, bout, Wkey, bkey,
                                                 alpha, gma, out);
}